// round 14
// baseline (speedup 1.0000x reference)
#include <cuda_runtime.h>
#include <math.h>

// B=256, T=512, C=512, L=64
#define BN 256
#define TN 512
#define CN 512
#define LN 64
#define SN 129              // 2L+1
#define BLANK 511
#define EPSV 1e-7f
#define RS 32               // row-ring slots (30 rows in flight)
#define NGRP 16             // prologue commit groups (2 rows each)
#define WAITG 15            // outstanding groups during mainloop
#define KS 5                // states per lane
#define LN2F 0.6931471805599453f
#define FULL 0xffffffffu

// CTC forward DP: one warp per batch element, two time steps fused per
// iteration (round-13 winner), ring deepened to 32 slots (60KB in flight
// per warp) via dynamic shared memory to raise achieved HBM bandwidth.
// Blank-dedup smem gather; alpha in registers (5/lane); neighbors via
// shfl. Linear-space recursion + exact power-of-2 renorm (arithmetic and
// cadence identical to rounds 10/13; rel_err unchanged).
__global__ __launch_bounds__(32)
void ctc_deep_kernel(const int* __restrict__ labels,     // [B, L]
                     const float* __restrict__ y_pred,   // [B, T, C]
                     const int* __restrict__ in_len,     // [B, 1]
                     const int* __restrict__ lab_len,    // [B, 1]
                     float* __restrict__ out)            // [B, 1]
{
    extern __shared__ __align__(16) float rows_dyn[];    // [RS][CN] = 64KB
    float (*rows)[CN] = reinterpret_cast<float (*)[CN]>(rows_dyn);

    const int b    = blockIdx.x;
    const int lane = threadIdx.x;
    const bool oddlane = (lane & 1);

    __shared__ float fin[SN];
    __shared__ int   ecap_sh;

    // Extended labels: state s = KS*lane + j ; parity of s = parity of lane+j
    int  cls[KS];
    bool valid[KS];
    #pragma unroll
    for (int j = 0; j < KS; ++j) {
        int s = KS * lane + j;
        valid[j] = (s < SN);
        int c = BLANK;
        if (valid[j] && (s & 1)) c = labels[b * LN + (s >> 1)];
        cls[j] = valid[j] ? c : 0;
    }
    int cu2 = __shfl_up_sync(FULL, cls[KS - 2], 1);
    int cu1 = __shfl_up_sync(FULL, cls[KS - 1], 1);
    bool alw[KS];
    #pragma unroll
    for (int j = 0; j < KS; ++j) {
        int s   = KS * lane + j;
        int cm2 = (j >= 2) ? cls[j - 2] : ((j == 1) ? cu1 : cu2);
        alw[j] = valid[j] && (s >= 2) && (cls[j] != BLANK) && (cls[j] != cm2);
    }

    // Label-gather classes (blank handled via one broadcast load)
    const int lc0 = oddlane ? cls[0] : cls[1];
    const int lc1 = oddlane ? cls[2] : cls[3];
    const int lc2 = oddlane ? cls[4] : BLANK;

    const float* base  = y_pred + (size_t)b * TN * CN;
    const int    T_eff = in_len[b];

    // t = 0
    float a[KS];
    #pragma unroll
    for (int j = 0; j < KS; ++j) {
        int s = KS * lane + j;
        a[j] = (s < 2) ? (base[cls[j]] + EPSV) : 0.0f;
    }
    if (T_eff == 1) {
        #pragma unroll
        for (int j = 0; j < KS; ++j)
            if (valid[j]) fin[KS * lane + j] = a[j];
        if (lane == 0) ecap_sh = 0;
    }

    #define CPROW(ST)                                                          \
        do {                                                                   \
            _Pragma("unroll")                                                  \
            for (int k = 0; k < 4; ++k) {                                      \
                unsigned dst = (unsigned)__cvta_generic_to_shared(             \
                    &rows[(ST) & (RS - 1)][lane * 4 + k * 128]);               \
                const float* src = base + (size_t)(ST) * CN + lane * 4 + k * 128; \
                asm volatile("cp.async.cg.shared.global [%0], [%1], 16;"       \
                             :: "r"(dst), "l"(src));                           \
            }                                                                  \
        } while (0)

    // Prologue: NGRP groups, group g carries rows 2g+1, 2g+2 (rows 1..32)
    #pragma unroll
    for (int g = 0; g < NGRP; ++g) {
        CPROW(2 * g + 1);
        CPROW(2 * g + 2);
        asm volatile("cp.async.commit_group;");
    }

    int   E = 0, pend_e = 0;
    float pend_sc = 1.0f;

    #define GATHER(R, PB, P0, P1, P2)                                          \
        float PB = (R)[BLANK];                                                 \
        float P0 = (R)[lc0];                                                   \
        float P1 = (R)[lc1];                                                   \
        float P2 = (R)[lc2];

    #define STEP(PB, P0, P1, P2, SC, EP)                                       \
        do {                                                                   \
            float h1 = __shfl_up_sync(FULL, a[KS - 1], 1);                     \
            float h2 = __shfl_up_sync(FULL, a[KS - 2], 1);                     \
            if (lane == 0) { h1 = 0.0f; h2 = 0.0f; }                           \
            float pe_b = fmaf(PB, SC, EP);                                     \
            float pe_0 = fmaf(P0, SC, EP);                                     \
            float pe_1 = fmaf(P1, SC, EP);                                     \
            float pe_2 = fmaf(P2, SC, EP);                                     \
            float pe[KS];                                                      \
            pe[0] = oddlane ? pe_0 : pe_b;                                     \
            pe[1] = oddlane ? pe_b : pe_0;                                     \
            pe[2] = oddlane ? pe_1 : pe_b;                                     \
            pe[3] = oddlane ? pe_b : pe_1;                                     \
            pe[4] = oddlane ? pe_2 : pe_b;                                     \
            _Pragma("unroll")                                                  \
            for (int j = 0; j < KS; ++j) if (!valid[j]) pe[j] = 0.0f;          \
            float n0 = (a[0] + h1   + (alw[0] ? h2   : 0.0f)) * pe[0];         \
            float n1 = (a[1] + a[0] + (alw[1] ? h1   : 0.0f)) * pe[1];         \
            float n2 = (a[2] + a[1] + (alw[2] ? a[0] : 0.0f)) * pe[2];         \
            float n3 = (a[3] + a[2] + (alw[3] ? a[1] : 0.0f)) * pe[3];         \
            float n4 = (a[4] + a[3] + (alw[4] ? a[2] : 0.0f)) * pe[4];         \
            a[0] = n0; a[1] = n1; a[2] = n2; a[3] = n3; a[4] = n4;             \
        } while (0)

    #define FINCHK(T)                                                          \
        if ((T) == T_eff - 1) {                                                \
            _Pragma("unroll")                                                  \
            for (int j = 0; j < KS; ++j)                                       \
                if (valid[j]) fin[KS * lane + j] = a[j];                       \
            if (lane == 0) ecap_sh = E;                                        \
        }

    #pragma unroll 4
    for (int pr = 0; pr < 255; ++pr) {
        const int t0 = 2 * pr + 1;
        const int t1 = t0 + 1;

        float sc512 = 512.0f * pend_sc;
        float epssc = (512.0f * EPSV) * pend_sc;
        E += pend_e; pend_e = 0; pend_sc = 1.0f;

        // NGRP+pr groups committed; wait<=WAITG -> groups 0..pr complete
        // -> rows up to 2pr+2 = t1 resident
        asm volatile("cp.async.wait_group %0;" :: "n"(WAITG));
        __syncwarp();

        const float* r0 = rows[t0 & (RS - 1)];
        const float* r1 = rows[t1 & (RS - 1)];
        GATHER(r0, pb0, pl00, pl01, pl02);
        GATHER(r1, pb1, pl10, pl11, pl12);

        // Refill: one group carrying rows t0+RS, t1+RS (guarded)
        {
            int s0 = t0 + RS, s1 = t1 + RS;
            if (s0 < TN) CPROW(s0);
            if (s1 < TN) CPROW(s1);
            asm volatile("cp.async.commit_group;");
        }

        STEP(pb0, pl00, pl01, pl02, sc512, epssc);
        FINCHK(t0);

        STEP(pb1, pl10, pl11, pl12, 512.0f, 512.0f * EPSV);

        if ((t1 & 7) == 0) {
            unsigned u = __float_as_uint(a[0]);
            u = max(u, __float_as_uint(a[1]));
            u = max(u, __float_as_uint(a[2]));
            u = max(u, __float_as_uint(a[3]));
            u = max(u, __float_as_uint(a[4]));
            u = __reduce_max_sync(FULL, u);
            int e = (int)(u >> 23) - 127;
            pend_e  = e;
            pend_sc = __uint_as_float((unsigned)(127 - e) << 23);  // 2^-e exact
        }
        FINCHK(t1);
    }

    // Epilogue: t = 511
    {
        const int t = TN - 1;
        float sc512 = 512.0f * pend_sc;
        float epssc = (512.0f * EPSV) * pend_sc;
        E += pend_e; pend_e = 0; pend_sc = 1.0f;

        asm volatile("cp.async.wait_group 0;");
        __syncwarp();

        const float* r0 = rows[t & (RS - 1)];
        GATHER(r0, pbe, ple0, ple1, ple2);
        STEP(pbe, ple0, ple1, ple2, sc512, epssc);
        FINCHK(t);
    }
    __syncwarp();

    if (lane == 0) {
        int ll = lab_len[b];
        int i1 = 2 * ll;
        int i2 = 2 * ll - 1;
        if (i1 < 0) i1 += SN;
        if (i2 < 0) i2 += SN;
        float x = fin[i1] + fin[i2];
        // stored = true * 2^(9*(T_eff-1) - ecap)
        out[b] = -logf(x) + ((float)(9 * (T_eff - 1) - ecap_sh)) * LN2F;
    }
}

extern "C" void kernel_launch(void* const* d_in, const int* in_sizes, int n_in,
                              void* d_out, int out_size)
{
    const int*   y_true       = (const int*)d_in[0];
    const float* y_pred       = (const float*)d_in[1];
    const int*   input_length = (const int*)d_in[2];
    const int*   label_length = (const int*)d_in[3];
    float*       out          = (float*)d_out;

    const int dyn_smem = RS * CN * (int)sizeof(float);   // 64KB ring
    // Idempotent, host-side attribute set (no allocation; capture-safe)
    cudaFuncSetAttribute(ctc_deep_kernel,
                         cudaFuncAttributeMaxDynamicSharedMemorySize, dyn_smem);

    ctc_deep_kernel<<<BN, 32, dyn_smem>>>(y_true, y_pred, input_length,
                                          label_length, out);
}

// round 15
// speedup vs baseline: 1.0723x; 1.0723x over previous
#include <cuda_runtime.h>
#include <math.h>

// B=256, T=512, C=512, L=64
#define BN 256
#define TN 512
#define CN 512
#define LN 64
#define SN 129              // 2L+1
#define BLANK 511
#define EPSV 1e-7f
#define RS 16               // row-ring slots (ring indexed t & 15)
#define KS 5                // states per lane
#define LN2F 0.6931471805599453f
#define FULL 0xffffffffu

// CTC forward DP: one warp per batch element, two time steps fused per
// iteration (round-13 winner), with the per-pair __syncwarp removed: the
// mainloop is warp-convergent, so wait_group (a warp-wide instruction)
// already guarantees all lanes' cp.async groups are complete before any
// lane's subsequent LDS issues; WAR on the recycled slot is ordered by
// program order under convergence. Blank-dedup smem gather; alpha in
// registers (5/lane); neighbors via shfl. Linear-space recursion + exact
// power-of-2 renorm (arithmetic identical to rounds 10/13).
__global__ __launch_bounds__(32, 4)
void ctc_nsync_kernel(const int* __restrict__ labels,     // [B, L]
                      const float* __restrict__ y_pred,   // [B, T, C]
                      const int* __restrict__ in_len,     // [B, 1]
                      const int* __restrict__ lab_len,    // [B, 1]
                      float* __restrict__ out)            // [B, 1]
{
    const int b    = blockIdx.x;
    const int lane = threadIdx.x;
    const bool oddlane = (lane & 1);

    __shared__ __align__(16) float rows[RS][CN];   // 32KB ring
    __shared__ float fin[SN];
    __shared__ int   ecap_sh;

    // Extended labels: state s = KS*lane + j ; parity of s = parity of lane+j
    int  cls[KS];
    bool valid[KS];
    #pragma unroll
    for (int j = 0; j < KS; ++j) {
        int s = KS * lane + j;
        valid[j] = (s < SN);
        int c = BLANK;
        if (valid[j] && (s & 1)) c = labels[b * LN + (s >> 1)];
        cls[j] = valid[j] ? c : 0;
    }
    int cu2 = __shfl_up_sync(FULL, cls[KS - 2], 1);
    int cu1 = __shfl_up_sync(FULL, cls[KS - 1], 1);
    bool alw[KS];
    #pragma unroll
    for (int j = 0; j < KS; ++j) {
        int s   = KS * lane + j;
        int cm2 = (j >= 2) ? cls[j - 2] : ((j == 1) ? cu1 : cu2);
        alw[j] = valid[j] && (s >= 2) && (cls[j] != BLANK) && (cls[j] != cm2);
    }

    // Label-gather classes (blank handled via one broadcast load)
    const int lc0 = oddlane ? cls[0] : cls[1];
    const int lc1 = oddlane ? cls[2] : cls[3];
    const int lc2 = oddlane ? cls[4] : BLANK;

    const float* base  = y_pred + (size_t)b * TN * CN;
    const int    T_eff = in_len[b];

    // t = 0
    float a[KS];
    #pragma unroll
    for (int j = 0; j < KS; ++j) {
        int s = KS * lane + j;
        a[j] = (s < 2) ? (base[cls[j]] + EPSV) : 0.0f;
    }
    if (T_eff == 1) {
        #pragma unroll
        for (int j = 0; j < KS; ++j)
            if (valid[j]) fin[KS * lane + j] = a[j];
        if (lane == 0) ecap_sh = 0;
    }

    #define CPROW(ST)                                                          \
        do {                                                                   \
            _Pragma("unroll")                                                  \
            for (int k = 0; k < 4; ++k) {                                      \
                unsigned dst = (unsigned)__cvta_generic_to_shared(             \
                    &rows[(ST) & (RS - 1)][lane * 4 + k * 128]);               \
                const float* src = base + (size_t)(ST) * CN + lane * 4 + k * 128; \
                asm volatile("cp.async.cg.shared.global [%0], [%1], 16;"       \
                             :: "r"(dst), "l"(src));                           \
            }                                                                  \
        } while (0)

    // Prologue: 8 groups, group g carries rows 2g+1, 2g+2 (rows 1..16)
    #pragma unroll
    for (int g = 0; g < 8; ++g) {
        CPROW(2 * g + 1);
        CPROW(2 * g + 2);
        asm volatile("cp.async.commit_group;");
    }

    int   E = 0, pend_e = 0;
    float pend_sc = 1.0f;

    #define GATHER(R, PB, P0, P1, P2)                                          \
        float PB = (R)[BLANK];                                                 \
        float P0 = (R)[lc0];                                                   \
        float P1 = (R)[lc1];                                                   \
        float P2 = (R)[lc2];

    #define STEP(PB, P0, P1, P2, SC, EP)                                       \
        do {                                                                   \
            float h1 = __shfl_up_sync(FULL, a[KS - 1], 1);                     \
            float h2 = __shfl_up_sync(FULL, a[KS - 2], 1);                     \
            if (lane == 0) { h1 = 0.0f; h2 = 0.0f; }                           \
            float pe_b = fmaf(PB, SC, EP);                                     \
            float pe_0 = fmaf(P0, SC, EP);                                     \
            float pe_1 = fmaf(P1, SC, EP);                                     \
            float pe_2 = fmaf(P2, SC, EP);                                     \
            float pe[KS];                                                      \
            pe[0] = oddlane ? pe_0 : pe_b;                                     \
            pe[1] = oddlane ? pe_b : pe_0;                                     \
            pe[2] = oddlane ? pe_1 : pe_b;                                     \
            pe[3] = oddlane ? pe_b : pe_1;                                     \
            pe[4] = oddlane ? pe_2 : pe_b;                                     \
            _Pragma("unroll")                                                  \
            for (int j = 0; j < KS; ++j) if (!valid[j]) pe[j] = 0.0f;          \
            float n0 = (a[0] + h1   + (alw[0] ? h2   : 0.0f)) * pe[0];         \
            float n1 = (a[1] + a[0] + (alw[1] ? h1   : 0.0f)) * pe[1];         \
            float n2 = (a[2] + a[1] + (alw[2] ? a[0] : 0.0f)) * pe[2];         \
            float n3 = (a[3] + a[2] + (alw[3] ? a[1] : 0.0f)) * pe[3];         \
            float n4 = (a[4] + a[3] + (alw[4] ? a[2] : 0.0f)) * pe[4];         \
            a[0] = n0; a[1] = n1; a[2] = n2; a[3] = n3; a[4] = n4;             \
        } while (0)

    #define FINCHK(T)                                                          \
        if ((T) == T_eff - 1) {                                                \
            _Pragma("unroll")                                                  \
            for (int j = 0; j < KS; ++j)                                       \
                if (valid[j]) fin[KS * lane + j] = a[j];                       \
            if (lane == 0) ecap_sh = E;                                        \
        }

    #pragma unroll 4
    for (int pr = 0; pr < 255; ++pr) {
        const int t0 = 2 * pr + 1;
        const int t1 = t0 + 1;

        // Apply pending renorm (only ever set after even t)
        float sc512 = 512.0f * pend_sc;
        float epssc = (512.0f * EPSV) * pend_sc;
        E += pend_e; pend_e = 0; pend_sc = 1.0f;

        // wait<=7: with 8+pr groups committed, groups 0..pr complete ->
        // rows up to 2pr+2 = t1 resident. Warp-wide instruction; under
        // convergent execution all lanes' groups are done before any lane
        // proceeds, so no __syncwarp is needed for cross-lane visibility.
        asm volatile("cp.async.wait_group %0;" :: "n"(7));

        // Both gathers up front (row t1's LDS latency hides under step t0)
        const float* r0 = rows[t0 & (RS - 1)];
        const float* r1 = rows[t1 & (RS - 1)];
        GATHER(r0, pb0, pl00, pl01, pl02);
        GATHER(r1, pb1, pl10, pl11, pl12);

        // Refill: one group carrying rows t0+16, t1+16 (guard each).
        // Program order (convergent warp) puts these after the GATHER LDS,
        // so recycling slot (t-1)&15 is WAR-safe.
        {
            int s0 = t0 + RS, s1 = t1 + RS;
            if (s0 < TN) CPROW(s0);
            if (s1 < TN) CPROW(s1);
            asm volatile("cp.async.commit_group;");
        }

        // Step t0 (odd t never triggers renorm)
        STEP(pb0, pl00, pl01, pl02, sc512, epssc);
        FINCHK(t0);

        // Step t1 (no pending renorm between t0 and t1)
        STEP(pb1, pl10, pl11, pl12, 512.0f, 512.0f * EPSV);

        if ((t1 & 7) == 0) {
            unsigned u = __float_as_uint(a[0]);
            u = max(u, __float_as_uint(a[1]));
            u = max(u, __float_as_uint(a[2]));
            u = max(u, __float_as_uint(a[3]));
            u = max(u, __float_as_uint(a[4]));
            u = __reduce_max_sync(FULL, u);
            int e = (int)(u >> 23) - 127;
            pend_e  = e;
            pend_sc = __uint_as_float((unsigned)(127 - e) << 23);  // 2^-e exact
        }
        FINCHK(t1);
    }

    // Epilogue: t = 511 (row 511 loaded by refill at pr=247, slot 15)
    {
        const int t = TN - 1;
        float sc512 = 512.0f * pend_sc;
        float epssc = (512.0f * EPSV) * pend_sc;
        E += pend_e; pend_e = 0; pend_sc = 1.0f;

        asm volatile("cp.async.wait_group 0;");

        const float* r0 = rows[t & (RS - 1)];
        GATHER(r0, pbe, ple0, ple1, ple2);
        STEP(pbe, ple0, ple1, ple2, sc512, epssc);
        FINCHK(t);
    }
    __syncwarp();   // fin[] handoff to lane 0 (load-bearing)

    if (lane == 0) {
        int ll = lab_len[b];
        int i1 = 2 * ll;
        int i2 = 2 * ll - 1;
        if (i1 < 0) i1 += SN;
        if (i2 < 0) i2 += SN;
        float x = fin[i1] + fin[i2];
        // stored = true * 2^(9*(T_eff-1) - ecap)
        out[b] = -logf(x) + ((float)(9 * (T_eff - 1) - ecap_sh)) * LN2F;
    }
}

extern "C" void kernel_launch(void* const* d_in, const int* in_sizes, int n_in,
                              void* d_out, int out_size)
{
    const int*   y_true       = (const int*)d_in[0];
    const float* y_pred       = (const float*)d_in[1];
    const int*   input_length = (const int*)d_in[2];
    const int*   label_length = (const int*)d_in[3];
    float*       out          = (float*)d_out;

    ctc_nsync_kernel<<<BN, 32>>>(y_true, y_pred, input_length, label_length, out);
}

// round 16
// speedup vs baseline: 1.1227x; 1.0470x over previous
#include <cuda_runtime.h>
#include <math.h>

// B=256, T=512, C=512, L=64
#define BN 256
#define TN 512
#define CN 512
#define LN 64
#define SN 129              // 2L+1
#define BLANK 511
#define EPSV 1e-7f
#define RS 16               // row-ring slots (ring indexed t & 15)
#define KS 5                // states per lane
#define LN2F 0.6931471805599453f
#define FULL 0xffffffffu
#define EP512 (512.0f * EPSV)

// CTC forward DP: one warp per batch element, two fused steps/iteration
// (round-13 skeleton). Instruction-diet fast path for T_eff == TN:
//  - no per-step valid masking (invalid states evolve harmlessly; masked
//    only inside the renorm max reduction)
//  - renorm applied directly to alpha registers (exact 2^-e multiply,
//    bit-identical: pow2 scaling commutes with fp32 rounding) -> pe uses
//    compile-time constants, no per-pair scale bookkeeping
//  - unguarded refill mainloop (pairs 0..246) + small guarded tail
//  - fin captured once at the epilogue
// Generic (r13-style) path retained for T_eff != TN.
__global__ __launch_bounds__(32, 4)
void ctc_diet_kernel(const int* __restrict__ labels,     // [B, L]
                     const float* __restrict__ y_pred,   // [B, T, C]
                     const int* __restrict__ in_len,     // [B, 1]
                     const int* __restrict__ lab_len,    // [B, 1]
                     float* __restrict__ out)            // [B, 1]
{
    const int b    = blockIdx.x;
    const int lane = threadIdx.x;
    const bool oddlane = (lane & 1);

    __shared__ __align__(16) float rows[RS][CN];   // 32KB ring
    __shared__ float fin[SN];
    __shared__ int   ecap_sh;

    // Extended labels: state s = KS*lane + j ; parity of s = parity of lane+j
    int  cls[KS];
    bool valid[KS];
    #pragma unroll
    for (int j = 0; j < KS; ++j) {
        int s = KS * lane + j;
        valid[j] = (s < SN);
        int c = BLANK;
        if (valid[j] && (s & 1)) c = labels[b * LN + (s >> 1)];
        cls[j] = valid[j] ? c : 0;
    }
    int cu2 = __shfl_up_sync(FULL, cls[KS - 2], 1);
    int cu1 = __shfl_up_sync(FULL, cls[KS - 1], 1);
    bool alw[KS];
    #pragma unroll
    for (int j = 0; j < KS; ++j) {
        int s   = KS * lane + j;
        int cm2 = (j >= 2) ? cls[j - 2] : ((j == 1) ? cu1 : cu2);
        alw[j] = valid[j] && (s >= 2) && (cls[j] != BLANK) && (cls[j] != cm2);
    }

    // Renorm masks (AND, not SEL): invalid regs contribute 0 to the max
    unsigned vm[KS];
    #pragma unroll
    for (int j = 0; j < KS; ++j) vm[j] = valid[j] ? 0xffffffffu : 0u;

    // Label-gather classes (blank via one broadcast load)
    const int lc0 = oddlane ? cls[0] : cls[1];
    const int lc1 = oddlane ? cls[2] : cls[3];
    const int lc2 = oddlane ? cls[4] : BLANK;

    const float* base  = y_pred + (size_t)b * TN * CN;
    const int    T_eff = in_len[b];

    // t = 0
    float a[KS];
    #pragma unroll
    for (int j = 0; j < KS; ++j) {
        int s = KS * lane + j;
        a[j] = (s < 2) ? (base[cls[j]] + EPSV) : 0.0f;
    }
    if (T_eff == 1) {
        #pragma unroll
        for (int j = 0; j < KS; ++j)
            if (valid[j]) fin[KS * lane + j] = a[j];
        if (lane == 0) ecap_sh = 0;
    }

    #define CPROW(ST)                                                          \
        do {                                                                   \
            _Pragma("unroll")                                                  \
            for (int k = 0; k < 4; ++k) {                                      \
                unsigned dst = (unsigned)__cvta_generic_to_shared(             \
                    &rows[(ST) & (RS - 1)][lane * 4 + k * 128]);               \
                const float* src = base + (size_t)(ST) * CN + lane * 4 + k * 128; \
                asm volatile("cp.async.cg.shared.global [%0], [%1], 16;"       \
                             :: "r"(dst), "l"(src));                           \
            }                                                                  \
        } while (0)

    // Prologue: 8 groups, group g carries rows 2g+1, 2g+2 (rows 1..16)
    #pragma unroll
    for (int g = 0; g < 8; ++g) {
        CPROW(2 * g + 1);
        CPROW(2 * g + 2);
        asm volatile("cp.async.commit_group;");
    }

    #define GATHER(R, PB, P0, P1, P2)                                          \
        float PB = (R)[BLANK];                                                 \
        float P0 = (R)[lc0];                                                   \
        float P1 = (R)[lc1];                                                   \
        float P2 = (R)[lc2];

    // Fast-path step: constant scale, NO validity masking
    #define STEPF(PB, P0, P1, P2)                                              \
        do {                                                                   \
            float h1 = __shfl_up_sync(FULL, a[KS - 1], 1);                     \
            float h2 = __shfl_up_sync(FULL, a[KS - 2], 1);                     \
            if (lane == 0) { h1 = 0.0f; h2 = 0.0f; }                           \
            float pe_b = fmaf(PB, 512.0f, EP512);                              \
            float pe_0 = fmaf(P0, 512.0f, EP512);                              \
            float pe_1 = fmaf(P1, 512.0f, EP512);                              \
            float pe_2 = fmaf(P2, 512.0f, EP512);                              \
            float q0 = oddlane ? pe_0 : pe_b;                                  \
            float q1 = oddlane ? pe_b : pe_0;                                  \
            float q2 = oddlane ? pe_1 : pe_b;                                  \
            float q3 = oddlane ? pe_b : pe_1;                                  \
            float q4 = oddlane ? pe_2 : pe_b;                                  \
            float n0 = (a[0] + h1   + (alw[0] ? h2   : 0.0f)) * q0;            \
            float n1 = (a[1] + a[0] + (alw[1] ? h1   : 0.0f)) * q1;            \
            float n2 = (a[2] + a[1] + (alw[2] ? a[0] : 0.0f)) * q2;            \
            float n3 = (a[3] + a[2] + (alw[3] ? a[1] : 0.0f)) * q3;            \
            float n4 = (a[4] + a[3] + (alw[4] ? a[2] : 0.0f)) * q4;            \
            a[0] = n0; a[1] = n1; a[2] = n2; a[3] = n3; a[4] = n4;             \
        } while (0)

    // Generic-path step (validity-masked, runtime scale) — r13 semantics
    #define STEPG(PB, P0, P1, P2, SC, EP)                                      \
        do {                                                                   \
            float h1 = __shfl_up_sync(FULL, a[KS - 1], 1);                     \
            float h2 = __shfl_up_sync(FULL, a[KS - 2], 1);                     \
            if (lane == 0) { h1 = 0.0f; h2 = 0.0f; }                           \
            float pe_b = fmaf(PB, SC, EP);                                     \
            float pe_0 = fmaf(P0, SC, EP);                                     \
            float pe_1 = fmaf(P1, SC, EP);                                     \
            float pe_2 = fmaf(P2, SC, EP);                                     \
            float pe[KS];                                                      \
            pe[0] = oddlane ? pe_0 : pe_b;                                     \
            pe[1] = oddlane ? pe_b : pe_0;                                     \
            pe[2] = oddlane ? pe_1 : pe_b;                                     \
            pe[3] = oddlane ? pe_b : pe_1;                                     \
            pe[4] = oddlane ? pe_2 : pe_b;                                     \
            _Pragma("unroll")                                                  \
            for (int j = 0; j < KS; ++j) if (!valid[j]) pe[j] = 0.0f;          \
            float n0 = (a[0] + h1   + (alw[0] ? h2   : 0.0f)) * pe[0];         \
            float n1 = (a[1] + a[0] + (alw[1] ? h1   : 0.0f)) * pe[1];         \
            float n2 = (a[2] + a[1] + (alw[2] ? a[0] : 0.0f)) * pe[2];         \
            float n3 = (a[3] + a[2] + (alw[3] ? a[1] : 0.0f)) * pe[3];         \
            float n4 = (a[4] + a[3] + (alw[4] ? a[2] : 0.0f)) * pe[4];         \
            a[0] = n0; a[1] = n1; a[2] = n2; a[3] = n3; a[4] = n4;             \
        } while (0)

    int E = 0;

    if (T_eff == TN) {
        // ---------------- FAST PATH (T_eff == 512) ----------------
        // Renorm: masked max, exact 2^-e scale applied to a[] directly.
        #define RENORMF()                                                      \
            do {                                                               \
                unsigned u = __float_as_uint(a[0]) & vm[0];                    \
                u = max(u, __float_as_uint(a[1]) & vm[1]);                     \
                u = max(u, __float_as_uint(a[2]) & vm[2]);                     \
                u = max(u, __float_as_uint(a[3]) & vm[3]);                     \
                u = max(u, __float_as_uint(a[4]) & vm[4]);                     \
                u = __reduce_max_sync(FULL, u);                                \
                int e = (int)(u >> 23) - 127;                                  \
                E += e;                                                        \
                float sc = __uint_as_float((unsigned)(127 - e) << 23);         \
                a[0] *= sc; a[1] *= sc; a[2] *= sc; a[3] *= sc; a[4] *= sc;    \
            } while (0)

        // Mainloop: pairs 0..246 — refill unguarded (rows 17..510)
        #pragma unroll 4
        for (int pr = 0; pr < 247; ++pr) {
            const int t0 = 2 * pr + 1;
            const int t1 = t0 + 1;

            asm volatile("cp.async.wait_group %0;" :: "n"(7));

            const float* r0 = rows[t0 & (RS - 1)];
            const float* r1 = rows[t1 & (RS - 1)];
            GATHER(r0, pb0, pl00, pl01, pl02);
            GATHER(r1, pb1, pl10, pl11, pl12);

            CPROW(t0 + RS);
            CPROW(t1 + RS);
            asm volatile("cp.async.commit_group;");

            STEPF(pb0, pl00, pl01, pl02);
            STEPF(pb1, pl10, pl11, pl12);

            if ((t1 & 7) == 0) RENORMF();
        }

        // Tail: pairs 247..254 — guarded refill, empty commits keep counts
        for (int pr = 247; pr < 255; ++pr) {
            const int t0 = 2 * pr + 1;
            const int t1 = t0 + 1;

            asm volatile("cp.async.wait_group %0;" :: "n"(7));

            const float* r0 = rows[t0 & (RS - 1)];
            const float* r1 = rows[t1 & (RS - 1)];
            GATHER(r0, pb0, pl00, pl01, pl02);
            GATHER(r1, pb1, pl10, pl11, pl12);

            {
                int s0 = t0 + RS, s1 = t1 + RS;
                if (s0 < TN) CPROW(s0);
                if (s1 < TN) CPROW(s1);
                asm volatile("cp.async.commit_group;");
            }

            STEPF(pb0, pl00, pl01, pl02);
            STEPF(pb1, pl10, pl11, pl12);

            if ((t1 & 7) == 0) RENORMF();
        }

        // Epilogue: t = 511
        {
            asm volatile("cp.async.wait_group 0;");
            const float* r0 = rows[(TN - 1) & (RS - 1)];
            GATHER(r0, pbe, ple0, ple1, ple2);
            STEPF(pbe, ple0, ple1, ple2);

            #pragma unroll
            for (int j = 0; j < KS; ++j)
                if (valid[j]) fin[KS * lane + j] = a[j];
            if (lane == 0) ecap_sh = E;
        }
    } else {
        // ---------------- GENERIC PATH (r13 semantics) ----------------
        int   pend_e = 0;
        float pend_sc = 1.0f;

        #define FINCHK(T)                                                      \
            if ((T) == T_eff - 1) {                                            \
                _Pragma("unroll")                                              \
                for (int j = 0; j < KS; ++j)                                   \
                    if (valid[j]) fin[KS * lane + j] = a[j];                   \
                if (lane == 0) ecap_sh = E;                                    \
            }

        for (int pr = 0; pr < 255; ++pr) {
            const int t0 = 2 * pr + 1;
            const int t1 = t0 + 1;

            float sc512 = 512.0f * pend_sc;
            float epssc = EP512 * pend_sc;
            E += pend_e; pend_e = 0; pend_sc = 1.0f;

            asm volatile("cp.async.wait_group %0;" :: "n"(7));

            const float* r0 = rows[t0 & (RS - 1)];
            const float* r1 = rows[t1 & (RS - 1)];
            GATHER(r0, pb0, pl00, pl01, pl02);
            GATHER(r1, pb1, pl10, pl11, pl12);

            {
                int s0 = t0 + RS, s1 = t1 + RS;
                if (s0 < TN) CPROW(s0);
                if (s1 < TN) CPROW(s1);
                asm volatile("cp.async.commit_group;");
            }

            STEPG(pb0, pl00, pl01, pl02, sc512, epssc);
            FINCHK(t0);
            STEPG(pb1, pl10, pl11, pl12, 512.0f, EP512);

            if ((t1 & 7) == 0) {
                unsigned u = __float_as_uint(a[0]) & vm[0];
                u = max(u, __float_as_uint(a[1]) & vm[1]);
                u = max(u, __float_as_uint(a[2]) & vm[2]);
                u = max(u, __float_as_uint(a[3]) & vm[3]);
                u = max(u, __float_as_uint(a[4]) & vm[4]);
                u = __reduce_max_sync(FULL, u);
                int e = (int)(u >> 23) - 127;
                pend_e  = e;
                pend_sc = __uint_as_float((unsigned)(127 - e) << 23);
            }
            FINCHK(t1);
        }
        {
            const int t = TN - 1;
            float sc512 = 512.0f * pend_sc;
            float epssc = EP512 * pend_sc;
            E += pend_e; pend_e = 0; pend_sc = 1.0f;

            asm volatile("cp.async.wait_group 0;");
            const float* r0 = rows[t & (RS - 1)];
            GATHER(r0, pbe, ple0, ple1, ple2);
            STEPG(pbe, ple0, ple1, ple2, sc512, epssc);
            FINCHK(t);
        }
    }
    __syncwarp();   // fin[] handoff to lane 0

    if (lane == 0) {
        int ll = lab_len[b];
        int i1 = 2 * ll;
        int i2 = 2 * ll - 1;
        if (i1 < 0) i1 += SN;
        if (i2 < 0) i2 += SN;
        float x = fin[i1] + fin[i2];
        // stored = true * 2^(9*(T_eff-1) - ecap)
        out[b] = -logf(x) + ((float)(9 * (T_eff - 1) - ecap_sh)) * LN2F;
    }
}

extern "C" void kernel_launch(void* const* d_in, const int* in_sizes, int n_in,
                              void* d_out, int out_size)
{
    const int*   y_true       = (const int*)d_in[0];
    const float* y_pred       = (const float*)d_in[1];
    const int*   input_length = (const int*)d_in[2];
    const int*   label_length = (const int*)d_in[3];
    float*       out          = (float*)d_out;

    ctc_diet_kernel<<<BN, 32>>>(y_true, y_pred, input_length, label_length, out);
}

// round 17
// speedup vs baseline: 1.1347x; 1.0106x over previous
#include <cuda_runtime.h>
#include <math.h>

// B=256, T=512, C=512, L=64
#define BN 256
#define TN 512
#define CN 512
#define LN 64
#define SN 129              // 2L+1
#define BLANK 511
#define EPSV 1e-7f
#define RS 16               // row-ring slots (ring indexed t & 15)
#define LN2F 0.6931471805599453f
#define FULL 0xffffffffu
#define EP512 (512.0f * EPSV)

// CTC forward DP: one warp per batch element, two fused steps/iteration.
// State layout: s = 4*lane + j for j=0..3 (states 0..127); state 128 lives
// in a[4] of lane 31 only. Since parity(s) == parity(j), j=0/2 are ALWAYS
// blank and j=1/3 ALWAYS labels -> no parity routing selects, blank states
// structurally have no s-2 term, and each lane gathers just 2 label
// classes (lab[2l], lab[2l+1]) + one broadcast blank per row.
// Renorm applied directly to alpha regs (exact 2^-e, every 8 steps, masked
// max). cp.async 16-slot ring, unguarded mainloop + guarded tail for
// T_eff == TN; generic per-step path otherwise.
__global__ __launch_bounds__(32, 4)
void ctc_lay4_kernel(const int* __restrict__ labels,     // [B, L]
                     const float* __restrict__ y_pred,   // [B, T, C]
                     const int* __restrict__ in_len,     // [B, 1]
                     const int* __restrict__ lab_len,    // [B, 1]
                     float* __restrict__ out)            // [B, 1]
{
    const int b    = blockIdx.x;
    const int lane = threadIdx.x;

    __shared__ __align__(16) float rows[RS][CN];   // 32KB ring
    __shared__ float fin[SN];
    __shared__ int   ecap_sh;

    // This lane's two label classes (states 4l+1 -> lab[2l], 4l+3 -> lab[2l+1])
    const int c0 = labels[b * LN + 2 * lane];
    const int c1 = labels[b * LN + 2 * lane + 1];

    // alw for odd states: s>=2 and label differs from label two states back
    const int c1prev = __shfl_up_sync(FULL, c1, 1);     // lab[2l-1]
    const bool alw1 = (lane > 0) && (c0 != c1prev);     // s=4l+1 (lane0: s=1 -> false)
    const bool alw3 = (c1 != c0);                       // s=4l+3 (always >= 3)

    const float* base  = y_pred + (size_t)b * TN * CN;
    const int    T_eff = in_len[b];

    // t = 0: alpha0[0] = p_blank + eps (lane 0), alpha0[1] = p_lab0 + eps (lane 0)
    float a[5];
    a[0] = (lane == 0) ? (base[BLANK] + EPSV) : 0.0f;
    a[1] = (lane == 0) ? (base[c0]    + EPSV) : 0.0f;
    a[2] = 0.0f; a[3] = 0.0f; a[4] = 0.0f;

    if (T_eff == 1) {
        #pragma unroll
        for (int j = 0; j < 4; ++j) fin[4 * lane + j] = a[j];
        if (lane == 31) fin[128] = a[4];
        if (lane == 0)  ecap_sh = 0;
    }

    #define CPROW(ST)                                                          \
        do {                                                                   \
            _Pragma("unroll")                                                  \
            for (int k = 0; k < 4; ++k) {                                      \
                unsigned dst = (unsigned)__cvta_generic_to_shared(             \
                    &rows[(ST) & (RS - 1)][lane * 4 + k * 128]);               \
                const float* src = base + (size_t)(ST) * CN + lane * 4 + k * 128; \
                asm volatile("cp.async.cg.shared.global [%0], [%1], 16;"       \
                             :: "r"(dst), "l"(src));                           \
            }                                                                  \
        } while (0)

    // Prologue: 8 groups, group g carries rows 2g+1, 2g+2 (rows 1..16)
    #pragma unroll
    for (int g = 0; g < 8; ++g) {
        CPROW(2 * g + 1);
        CPROW(2 * g + 2);
        asm volatile("cp.async.commit_group;");
    }

    #define GATHER(R, PB, P0, P1)                                              \
        float PB = (R)[BLANK];                                                 \
        float P0 = (R)[c0];                                                    \
        float P1 = (R)[c1];

    // Fast-path step: constant scale. Blank states (j=0,2,4) have no s-2
    // term structurally; label states (j=1,3) carry their alw select.
    #define STEPF(PB, P0, P1)                                                  \
        do {                                                                   \
            float h1 = __shfl_up_sync(FULL, a[3], 1);   /* s-1 of state 4l */  \
            float h2 = __shfl_up_sync(FULL, a[2], 1);   /* unused by blanks */ \
            (void)h2;                                                          \
            if (lane == 0) h1 = 0.0f;                                          \
            float pe_b = fmaf(PB, 512.0f, EP512);                              \
            float pe_0 = fmaf(P0, 512.0f, EP512);                              \
            float pe_1 = fmaf(P1, 512.0f, EP512);                              \
            float n0 = (a[0] + h1) * pe_b;                                     \
            float n1 = (a[1] + a[0] + (alw1 ? h1   : 0.0f)) * pe_0;            \
            float n2 = (a[2] + a[1]) * pe_b;                                   \
            float n3 = (a[3] + a[2] + (alw3 ? a[1] : 0.0f)) * pe_1;            \
            float n4 = (a[4] + a[3]) * pe_b;   /* state 128 on lane 31 */      \
            a[0] = n0; a[1] = n1; a[2] = n2; a[3] = n3; a[4] = n4;             \
        } while (0)

    #define STEPG(PB, P0, P1, SC, EP)                                          \
        do {                                                                   \
            float h1 = __shfl_up_sync(FULL, a[3], 1);                          \
            if (lane == 0) h1 = 0.0f;                                          \
            float pe_b = fmaf(PB, SC, EP);                                     \
            float pe_0 = fmaf(P0, SC, EP);                                     \
            float pe_1 = fmaf(P1, SC, EP);                                     \
            float n0 = (a[0] + h1) * pe_b;                                     \
            float n1 = (a[1] + a[0] + (alw1 ? h1   : 0.0f)) * pe_0;            \
            float n2 = (a[2] + a[1]) * pe_b;                                   \
            float n3 = (a[3] + a[2] + (alw3 ? a[1] : 0.0f)) * pe_1;            \
            float n4 = (a[4] + a[3]) * pe_b;                                   \
            a[0] = n0; a[1] = n1; a[2] = n2; a[3] = n3; a[4] = n4;             \
        } while (0)

    // Renorm: a[0..3] valid on every lane; a[4] valid only on lane 31.
    const unsigned vm4 = (lane == 31) ? 0xffffffffu : 0u;

    int E = 0;

    if (T_eff == TN) {
        // ---------------- FAST PATH (T_eff == 512) ----------------
        #define RENORMF()                                                      \
            do {                                                               \
                unsigned u = __float_as_uint(a[0]);                            \
                u = max(u, __float_as_uint(a[1]));                             \
                u = max(u, __float_as_uint(a[2]));                             \
                u = max(u, __float_as_uint(a[3]));                             \
                u = max(u, __float_as_uint(a[4]) & vm4);                       \
                u = __reduce_max_sync(FULL, u);                                \
                int e = (int)(u >> 23) - 127;                                  \
                E += e;                                                        \
                float sc = __uint_as_float((unsigned)(127 - e) << 23);         \
                a[0] *= sc; a[1] *= sc; a[2] *= sc; a[3] *= sc; a[4] *= sc;    \
            } while (0)

        // Mainloop: pairs 0..246 — refill unguarded (rows 17..510)
        #pragma unroll 4
        for (int pr = 0; pr < 247; ++pr) {
            const int t0 = 2 * pr + 1;
            const int t1 = t0 + 1;

            asm volatile("cp.async.wait_group %0;" :: "n"(7));

            const float* r0 = rows[t0 & (RS - 1)];
            const float* r1 = rows[t1 & (RS - 1)];
            GATHER(r0, pb0, pl00, pl01);
            GATHER(r1, pb1, pl10, pl11);

            CPROW(t0 + RS);
            CPROW(t1 + RS);
            asm volatile("cp.async.commit_group;");

            STEPF(pb0, pl00, pl01);
            STEPF(pb1, pl10, pl11);

            if ((t1 & 7) == 0) RENORMF();
        }

        // Tail: pairs 247..254 — guarded refill keeps group counts uniform
        for (int pr = 247; pr < 255; ++pr) {
            const int t0 = 2 * pr + 1;
            const int t1 = t0 + 1;

            asm volatile("cp.async.wait_group %0;" :: "n"(7));

            const float* r0 = rows[t0 & (RS - 1)];
            const float* r1 = rows[t1 & (RS - 1)];
            GATHER(r0, pb0, pl00, pl01);
            GATHER(r1, pb1, pl10, pl11);

            {
                int s0 = t0 + RS, s1 = t1 + RS;
                if (s0 < TN) CPROW(s0);
                if (s1 < TN) CPROW(s1);
                asm volatile("cp.async.commit_group;");
            }

            STEPF(pb0, pl00, pl01);
            STEPF(pb1, pl10, pl11);

            if ((t1 & 7) == 0) RENORMF();
        }

        // Epilogue: t = 511
        {
            asm volatile("cp.async.wait_group 0;");
            const float* r0 = rows[(TN - 1) & (RS - 1)];
            GATHER(r0, pbe, ple0, ple1);
            STEPF(pbe, ple0, ple1);

            #pragma unroll
            for (int j = 0; j < 4; ++j) fin[4 * lane + j] = a[j];
            if (lane == 31) fin[128] = a[4];
            if (lane == 0)  ecap_sh = E;
        }
    } else {
        // ---------------- GENERIC PATH (any T_eff) ----------------
        int   pend_e = 0;
        float pend_sc = 1.0f;

        #define FINCHK(T)                                                      \
            if ((T) == T_eff - 1) {                                            \
                _Pragma("unroll")                                              \
                for (int j = 0; j < 4; ++j) fin[4 * lane + j] = a[j];          \
                if (lane == 31) fin[128] = a[4];                               \
                if (lane == 0)  ecap_sh = E;                                   \
            }

        for (int pr = 0; pr < 255; ++pr) {
            const int t0 = 2 * pr + 1;
            const int t1 = t0 + 1;

            float sc512 = 512.0f * pend_sc;
            float epssc = EP512 * pend_sc;
            E += pend_e; pend_e = 0; pend_sc = 1.0f;

            asm volatile("cp.async.wait_group %0;" :: "n"(7));

            const float* r0 = rows[t0 & (RS - 1)];
            const float* r1 = rows[t1 & (RS - 1)];
            GATHER(r0, pb0, pl00, pl01);
            GATHER(r1, pb1, pl10, pl11);

            {
                int s0 = t0 + RS, s1 = t1 + RS;
                if (s0 < TN) CPROW(s0);
                if (s1 < TN) CPROW(s1);
                asm volatile("cp.async.commit_group;");
            }

            STEPG(pb0, pl00, pl01, sc512, epssc);
            FINCHK(t0);
            STEPG(pb1, pl10, pl11, 512.0f, EP512);

            if ((t1 & 7) == 0) {
                unsigned u = __float_as_uint(a[0]);
                u = max(u, __float_as_uint(a[1]));
                u = max(u, __float_as_uint(a[2]));
                u = max(u, __float_as_uint(a[3]));
                u = max(u, __float_as_uint(a[4]) & vm4);
                u = __reduce_max_sync(FULL, u);
                int e = (int)(u >> 23) - 127;
                pend_e  = e;
                pend_sc = __uint_as_float((unsigned)(127 - e) << 23);
            }
            FINCHK(t1);
        }
        {
            const int t = TN - 1;
            float sc512 = 512.0f * pend_sc;
            float epssc = EP512 * pend_sc;
            E += pend_e; pend_e = 0; pend_sc = 1.0f;

            asm volatile("cp.async.wait_group 0;");
            const float* r0 = rows[t & (RS - 1)];
            GATHER(r0, pbe, ple0, ple1);
            STEPG(pbe, ple0, ple1, sc512, epssc);
            FINCHK(t);
        }
    }
    __syncwarp();   // fin[] handoff to lane 0

    if (lane == 0) {
        int ll = lab_len[b];
        int i1 = 2 * ll;
        int i2 = 2 * ll - 1;
        if (i1 < 0) i1 += SN;
        if (i2 < 0) i2 += SN;
        float x = fin[i1] + fin[i2];
        // stored = true * 2^(9*(T_eff-1) - ecap)
        out[b] = -logf(x) + ((float)(9 * (T_eff - 1) - ecap_sh)) * LN2F;
    }
}

extern "C" void kernel_launch(void* const* d_in, const int* in_sizes, int n_in,
                              void* d_out, int out_size)
{
    const int*   y_true       = (const int*)d_in[0];
    const float* y_pred       = (const float*)d_in[1];
    const int*   input_length = (const int*)d_in[2];
    const int*   label_length = (const int*)d_in[3];
    float*       out          = (float*)d_out;

    ctc_lay4_kernel<<<BN, 32>>>(y_true, y_pred, input_length, label_length, out);
}